// round 10
// baseline (speedup 1.0000x reference)
#include <cuda_runtime.h>
#include <cuda_fp16.h>
#include <cuda_bf16.h>

#define B 512
#define S 1024
#define I 20
#define H 64
#define G 256     // 4*H gates
#define NB 4      // batches per LSTM CTA -> grid (128,2) = 256 CTAs, ~2/SM
#define WROW 264  // padded float stride of s_Wihb rows (bank shift 8)
#define GWST 72   // per-batch float stride in warp gate region (bank shift 8)
#define HST 80    // half stride of h rows (word stride 40 -> bank shift 8)

// ---- scratch (device globals; no allocation allowed) ----
__device__ int   g_tok[B * S];
__device__ int   g_len[B];
__device__ float g_h[2][B * H];
__device__ float g_avblock[B * 80];

__device__ __forceinline__ unsigned pack_h2(float lo, float hi) {
    __half2 h = __floats2half2_rn(lo, hi);
    return *reinterpret_cast<unsigned*>(&h);
}
__device__ __forceinline__ __half2 h2tanh_fast(__half2 x) {
    unsigned xi = *reinterpret_cast<unsigned*>(&x);
    unsigned yi;
    asm("tanh.approx.f16x2 %0, %1;" : "=r"(yi) : "r"(xi));
    return *reinterpret_cast<__half2*>(&yi);
}
__device__ __forceinline__ __half2 sig2_fast(__half2 x, __half2 h05) {
    return __hfma2(h2tanh_fast(__hmul2(x, h05)), h05, h05);
}
__device__ __forceinline__ void mma_f16(float d[4],
                                        unsigned a0, unsigned a1,
                                        unsigned a2, unsigned a3,
                                        unsigned b0, unsigned b1) {
    asm volatile(
        "mma.sync.aligned.m16n8k16.row.col.f32.f16.f16.f32 "
        "{%0,%1,%2,%3}, {%4,%5,%6,%7}, {%8,%9}, {%0,%1,%2,%3};"
        : "+f"(d[0]), "+f"(d[1]), "+f"(d[2]), "+f"(d[3])
        : "r"(a0), "r"(a1), "r"(a2), "r"(a3), "r"(b0), "r"(b1));
}

// ============================================================
// Kernel 1: tokenize one-hot input + compute lengths
// ============================================================
__global__ void k_tokenize(const float* __restrict__ input1) {
    int b = blockIdx.x;
    int tid = threadIdx.x;
    __shared__ int s_cnt[256];
    int cnt = 0;
    for (int s = tid; s < S; s += 256) {
        const float4* row = (const float4*)(input1 + ((size_t)b * S + s) * I);
        int t = -1;
        #pragma unroll
        for (int q = 0; q < 5; q++) {
            float4 v = row[q];
            if (v.x > 0.5f) t = q * 4 + 0;
            if (v.y > 0.5f) t = q * 4 + 1;
            if (v.z > 0.5f) t = q * 4 + 2;
            if (v.w > 0.5f) t = q * 4 + 3;
        }
        g_tok[b * S + s] = t;
        if (t >= 0) cnt++;
    }
    s_cnt[tid] = cnt;
    __syncthreads();
    for (int off = 128; off > 0; off >>= 1) {
        if (tid < off) s_cnt[tid] += s_cnt[tid + off];
        __syncthreads();
    }
    if (tid == 0) g_len[b] = s_cnt[0];
}

// ============================================================
// Kernel 2: fp16 tensor-core LSTM, gate-permuted + single barrier.
// 128 threads (4 warps), NB=4 batches. Transposed GEMM
//   D[256 perm-gates, 8 cols] = Wp[256,64] @ h~[64,8],
// B columns replicated x2 (col c <-> batch c>>1).
// Permutation: perm row 64w+16j+4*ut+gate <-> unit u=16w+4j+ut, gate
// (gate 0..3 = i,f,g,o) so warp w owns complete gate quads for units
// [16w,16w+16) of ALL batches -> activation is warp-local.
// One __syncthreads per step; h double-buffered.
// ============================================================
__global__ void __launch_bounds__(128, 2)
k_lstm(const float* __restrict__ W_ih_f, const float* __restrict__ W_hh_f,
       const float* __restrict__ b_f,
       const float* __restrict__ W_ih_b, const float* __restrict__ W_hh_b,
       const float* __restrict__ b_b) {
    int b0  = blockIdx.x * NB;
    int dir = blockIdx.y;
    int t    = threadIdx.x;
    int w    = t >> 5;         // warp 0..3
    int lane = t & 31;
    int gID  = lane >> 2;      // 0..7
    int tig  = lane & 3;       // 0..3  (= batch in D cols / act)

    const float* W_ih = dir ? W_ih_b : W_ih_f;
    const float* W_hh = dir ? W_hh_b : W_hh_f;
    const float* bias = dir ? b_b    : b_f;

    __shared__ float  s_Wihb[21 * WROW];     // [tok][4u+gate] bias-fused, permuted
    __shared__ float  s_gw[4 * 4 * GWST];    // [warp][batch][64 perm-local gates]
    __shared__ __half s_hbuf[2][4 * HST];    // ping-pong h, [batch][unit]
    __shared__ signed char s_tok[NB * S];

    // stage permuted W_ih (+bias); row 20 = bias only
    for (int idx = t; idx < 21 * 256; idx += 128) {
        int tok = idx >> 8;
        int pi  = idx & 255;
        int u    = pi >> 2;
        int gate = pi & 3;
        int orig = gate * 64 + u;
        float v = bias[orig];
        if (tok < I) v += W_ih[orig * I + tok];
        s_Wihb[tok * WROW + pi] = v;
    }
    for (int idx = t; idx < NB * S; idx += 128) {
        int nb = idx >> 10, s = idx & (S - 1);
        s_tok[idx] = (signed char)g_tok[(b0 + nb) * S + s];
    }
    for (int idx = t; idx < 2 * 4 * HST / 2; idx += 128)
        ((unsigned*)s_hbuf)[idx] = 0u;

    // A fragments: permuted W_hh rows, 4 tiles x 4 k-chunks
    unsigned af[4][4][4];
    {
        #pragma unroll
        for (int j = 0; j < 4; j++) {
            int u0 = 16 * w + 4 * j + (gID >> 2);
            int r0 = (gID & 3) * 64 + u0;      // perm row gID of tile j
            int r1 = r0 + 2;                   // perm row gID+8
            const float* p0 = W_hh + r0 * H;
            const float* p1 = W_hh + r1 * H;
            #pragma unroll
            for (int kt = 0; kt < 4; kt++) {
                int k0 = kt * 16 + 2 * tig;
                af[kt][j][0] = pack_h2(p0[k0],     p0[k0 + 1]);
                af[kt][j][1] = pack_h2(p1[k0],     p1[k0 + 1]);
                af[kt][j][2] = pack_h2(p0[k0 + 8], p0[k0 + 9]);
                af[kt][j][3] = pack_h2(p1[k0 + 8], p1[k0 + 9]);
            }
        }
    }

    // this lane's activation: batch tig, units ua = 16w+2gID, ua+1
    int ua = 16 * w + 2 * gID;
    float* gw = s_gw + w * (4 * GWST) + tig * GWST;
    float cs0 = 0.0f, cs1 = 0.0f;
    float hx = 0.0f, hy = 0.0f;
    const __half2 h05 = __float2half2_rn(0.5f);
    int p = 0;
    __syncthreads();

    for (int step = 0; step < S; step++) {
        int s = dir ? (S - 1 - step) : step;

        // ---- MMA: 16 mma/warp; B cols replicated (row = gID>>1) ----
        float d[4][4] = {{0.f,0.f,0.f,0.f},{0.f,0.f,0.f,0.f},
                         {0.f,0.f,0.f,0.f},{0.f,0.f,0.f,0.f}};
        {
            const __half* hb = s_hbuf[p] + (gID >> 1) * HST;
            #pragma unroll
            for (int kt = 0; kt < 4; kt++) {
                int k0 = kt * 16 + 2 * tig;
                unsigned bb0 = *(const unsigned*)(hb + k0);
                unsigned bb1 = *(const unsigned*)(hb + k0 + 8);
                #pragma unroll
                for (int j = 0; j < 4; j++)
                    mma_f16(d[j], af[kt][j][0], af[kt][j][1],
                                  af[kt][j][2], af[kt][j][3], bb0, bb1);
            }
        }
        // warp-local scatter: c0 -> perm row gID, c2 -> gID+8, batch tig
        #pragma unroll
        for (int j = 0; j < 4; j++) {
            gw[16 * j + gID]     = d[j][0];
            gw[16 * j + gID + 8] = d[j][2];
        }
        __syncwarp();

        // ---- warp-local activation: units ua, ua+1 of batch tig ----
        {
            int tok = s_tok[tig * S + s];
            int row = (tok >= 0) ? tok : 20;
            float4 ga = *(const float4*)(gw + 8 * gID);       // i,f,g,o unit ua
            float4 gb = *(const float4*)(gw + 8 * gID + 4);   // unit ua+1
            const float* ip = s_Wihb + row * WROW + 4 * ua;
            float4 wa = *(const float4*)(ip);
            float4 wb = *(const float4*)(ip + 4);
            __half2 I2 = __floats2half2_rn(ga.x + wa.x, gb.x + wb.x);
            __half2 F2 = __floats2half2_rn(ga.y + wa.y, gb.y + wb.y);
            __half2 G2 = __floats2half2_rn(ga.z + wa.z, gb.z + wb.z);
            __half2 O2 = __floats2half2_rn(ga.w + wa.w, gb.w + wb.w);
            __half2 sI = sig2_fast(I2, h05);
            __half2 sF = sig2_fast(F2, h05);
            __half2 sO = sig2_fast(O2, h05);
            __half2 tG = h2tanh_fast(G2);
            float2 fF = __half22float2(sF);
            float2 pp = __half22float2(__hmul2(sI, tG));
            cs0 = fF.x * cs0 + pp.x;
            cs1 = fF.y * cs1 + pp.y;
            __half2 tC = h2tanh_fast(__floats2half2_rn(cs0, cs1));
            __half2 hv = __hmul2(sO, tC);
            *(__half2*)(s_hbuf[p ^ 1] + tig * HST + ua) = hv;
            float2 fh = __half22float2(hv);
            hx = fh.x; hy = fh.y;
        }
        __syncthreads();
        p ^= 1;
    }

    *(float2*)(&g_h[dir][(b0 + tig) * H + ua]) = make_float2(hx, hy);
}

// ============================================================
// Kernel 3: conv1 (token gather) + torch-reshape + ragged 4-bin mean
// ============================================================
__global__ void k_avblock(const float* __restrict__ conv1_w) {
    int b = blockIdx.x;
    int tid = threadIdx.x;
    __shared__ int   s_tok[S];
    __shared__ float s_w[I * I];
    for (int s = tid; s < S; s += 128) s_tok[s] = g_tok[b * S + s];
    for (int i = tid; i < I * I; i += 128) s_w[i] = conv1_w[i];
    __syncthreads();

    int bw = g_len[b] / 4;
    if (tid < 80) {
        int k = tid / I, cc = tid % I;
        float sum = 0.0f;
        for (int s = k * bw; s < (k + 1) * bw; s++) {
            int flat = s * I + cc;
            int ch = flat >> 10;
            int pp = flat & (S - 1);
            int tk = s_tok[pp];
            if (tk >= 0) sum += s_w[ch * I + tk];
        }
        g_avblock[b * 80 + tid] = sum / (float)bw;
    }
}

// ============================================================
// Kernel 4: conv2+relu, concat, fc1, fc2, softmax
// ============================================================
__global__ void k_head(const float* __restrict__ conv2_w,
                       const float* __restrict__ conv2_b,
                       const float* __restrict__ fc1_w,
                       const float* __restrict__ fc1_b,
                       const float* __restrict__ fc2_w,
                       const float* __restrict__ fc2_b,
                       float* __restrict__ out) {
    int b = blockIdx.x;
    int tid = threadIdx.x;
    __shared__ float s_m[232];
    __shared__ float s_av[80];
    __shared__ float s_f[64];

    if (tid < 64)            s_m[tid] = g_h[0][b * H + tid];
    else if (tid < 128)      s_m[tid] = g_h[1][b * H + tid - 64];
    if (tid < 80)            s_av[tid] = g_avblock[b * 80 + tid];
    if (tid >= 100 && tid < 104) s_m[128 + tid] = 0.0f;
    __syncthreads();

    if (tid < 100) {
        float acc = conv2_b[tid];
        const float* w = conv2_w + tid * 80;
        float a0 = 0.f, a1 = 0.f, a2 = 0.f, a3 = 0.f;
        #pragma unroll
        for (int j = 0; j < 80; j += 4) {
            a0 = fmaf(s_av[j],     w[j],     a0);
            a1 = fmaf(s_av[j + 1], w[j + 1], a1);
            a2 = fmaf(s_av[j + 2], w[j + 2], a2);
            a3 = fmaf(s_av[j + 3], w[j + 3], a3);
        }
        s_m[128 + tid] = fmaxf(acc + (a0 + a1) + (a2 + a3), 0.0f);
    }
    __syncthreads();

    if (tid < 64) {
        const float* w = fc1_w + tid * 228;
        float a0 = 0.f, a1 = 0.f, a2 = 0.f, a3 = 0.f;
        for (int j = 0; j < 228; j += 4) {
            a0 = fmaf(s_m[j],     w[j],     a0);
            a1 = fmaf(s_m[j + 1], w[j + 1], a1);
            a2 = fmaf(s_m[j + 2], w[j + 2], a2);
            a3 = fmaf(s_m[j + 3], w[j + 3], a3);
        }
        s_f[tid] = fc1_b[tid] + (a0 + a1) + (a2 + a3);
    }
    __syncthreads();

    if (tid < 32) {
        float v0 = s_f[tid], v1 = s_f[tid + 32];
        float p0 = v0 * fc2_w[tid]      + v1 * fc2_w[tid + 32];
        float p1 = v0 * fc2_w[64 + tid] + v1 * fc2_w[96 + tid];
        #pragma unroll
        for (int o = 16; o > 0; o >>= 1) {
            p0 += __shfl_xor_sync(0xffffffffu, p0, o);
            p1 += __shfl_xor_sync(0xffffffffu, p1, o);
        }
        if (tid == 0) {
            float a0 = p0 + fc2_b[0], a1 = p1 + fc2_b[1];
            float m  = fmaxf(a0, a1);
            float e0 = __expf(a0 - m), e1 = __expf(a1 - m);
            float inv = 1.0f / (e0 + e1);
            out[b * 2 + 0] = e0 * inv;
            out[b * 2 + 1] = e1 * inv;
        }
    }
}

extern "C" void kernel_launch(void* const* d_in, const int* in_sizes, int n_in,
                              void* d_out, int out_size) {
    const float* input1  = (const float*)d_in[0];
    const float* W_ih_f  = (const float*)d_in[1];
    const float* W_hh_f  = (const float*)d_in[2];
    const float* b_f     = (const float*)d_in[3];
    const float* W_ih_b  = (const float*)d_in[4];
    const float* W_hh_b  = (const float*)d_in[5];
    const float* b_b     = (const float*)d_in[6];
    const float* conv1_w = (const float*)d_in[7];
    const float* conv2_w = (const float*)d_in[8];
    const float* conv2_b = (const float*)d_in[9];
    const float* fc1_w   = (const float*)d_in[10];
    const float* fc1_b   = (const float*)d_in[11];
    const float* fc2_w   = (const float*)d_in[12];
    const float* fc2_b   = (const float*)d_in[13];
    float* out = (float*)d_out;

    k_tokenize<<<B, 256>>>(input1);
    dim3 lgrid(B / NB, 2);
    k_lstm<<<lgrid, 128>>>(W_ih_f, W_hh_f, b_f, W_ih_b, W_hh_b, b_b);
    k_avblock<<<B, 128>>>(conv1_w);
    k_head<<<B, 128>>>(conv2_w, conv2_b, fc1_w, fc1_b, fc2_w, fc2_b, out);
}